// round 9
// baseline (speedup 1.0000x reference)
#include <cuda_runtime.h>

// Algebraic reduction of the reference (verified R2-R8, rel_err 1.41e-7):
//   tr = (op - op) * weight == 0 exactly  =>  real_sum == 0  =>
//   out[b] = relu(relu(bf1) @ Wf2^T + bf2) @ Wf3^T + bf3   (same scalar, all b)
// Live inputs: bf1, Wf2(128x128), bf2, Wf3, bf3 — located by anchoring on
// Wf1's unique element count (128*32768) in in_sizes.
//
// R9: R8's winning structure (1024 thr, 8 thr/row, 8x LDG.128/thread, one
// concurrent load window, predicate-free row fold, single barrier).
// Trims: bf3 loaded only by the 32 threads that use it (removes 992
// redundant scalar LDGs from the launch burst); explicit 5-shfl tail.
// We are within ~10% of the single-block T_ovh floor (~5000 cyc + ~2000 cyc
// work at NAT clock); if this round is neutral the kernel is terminal.

#define PF 128

__global__ __launch_bounds__(1024, 1)
void TF2N_35347580846484_kernel(const float* __restrict__ bf1,
                                const float* __restrict__ Wf2,
                                const float* __restrict__ bf2,
                                const float* __restrict__ Wf3,
                                const float* __restrict__ bf3,
                                float* __restrict__ out) {
    __shared__ float wsum[32];         // per-warp partial sums

    const int t = threadIdx.x;
    const int r = t >> 3;              // output row 0..127
    const int c = t & 7;               // 16-col chunk within the row

    // Issue ALL global loads up front; every one is independent.
    const float4* __restrict__ wp =
        reinterpret_cast<const float4*>(Wf2 + r * PF + c * 16);
    const float4* __restrict__ zp =
        reinterpret_cast<const float4*>(bf1 + c * 16);
    const float4 w0 = wp[0];
    const float4 w1 = wp[1];
    const float4 w2 = wp[2];
    const float4 w3 = wp[3];
    float4 a0 = zp[0];
    float4 a1 = zp[1];
    float4 a2 = zp[2];
    float4 a3 = zp[3];
    const float b2  = bf2[r];
    const float w3r = Wf3[r];

    // relu(bf1) in registers
    a0.x = fmaxf(a0.x, 0.0f); a0.y = fmaxf(a0.y, 0.0f);
    a0.z = fmaxf(a0.z, 0.0f); a0.w = fmaxf(a0.w, 0.0f);
    a1.x = fmaxf(a1.x, 0.0f); a1.y = fmaxf(a1.y, 0.0f);
    a1.z = fmaxf(a1.z, 0.0f); a1.w = fmaxf(a1.w, 0.0f);
    a2.x = fmaxf(a2.x, 0.0f); a2.y = fmaxf(a2.y, 0.0f);
    a2.z = fmaxf(a2.z, 0.0f); a2.w = fmaxf(a2.w, 0.0f);
    a3.x = fmaxf(a3.x, 0.0f); a3.y = fmaxf(a3.y, 0.0f);
    a3.z = fmaxf(a3.z, 0.0f); a3.w = fmaxf(a3.w, 0.0f);

    // 16-element partial dot: Wf2[r, c*16 .. c*16+15] . relu(bf1)[c*16..]
    float acc;
    acc = w0.x * a0.x;
    acc = fmaf(w0.y, a0.y, acc);
    acc = fmaf(w0.z, a0.z, acc);
    acc = fmaf(w0.w, a0.w, acc);
    acc = fmaf(w1.x, a1.x, acc);
    acc = fmaf(w1.y, a1.y, acc);
    acc = fmaf(w1.z, a1.z, acc);
    acc = fmaf(w1.w, a1.w, acc);
    acc = fmaf(w2.x, a2.x, acc);
    acc = fmaf(w2.y, a2.y, acc);
    acc = fmaf(w2.z, a2.z, acc);
    acc = fmaf(w2.w, a2.w, acc);
    acc = fmaf(w3.x, a3.x, acc);
    acc = fmaf(w3.y, a3.y, acc);
    acc = fmaf(w3.z, a3.z, acc);
    acc = fmaf(w3.w, a3.w, acc);

    // Reduce the 8 chunk-partials of this row; all 8 lanes end with the sum.
    acc += __shfl_xor_sync(0xffffffffu, acc, 1);
    acc += __shfl_xor_sync(0xffffffffu, acc, 2);
    acc += __shfl_xor_sync(0xffffffffu, acc, 4);

    // Every lane of the row group folds bias + relu + Wf3 weight (identical
    // value on all 8 lanes). The cross-group butterfly below sums one
    // representative per row group at each lane position -> exact 4-row sum.
    float contrib = fmaxf(acc + b2, 0.0f) * w3r;

    // Sum the 4 row-groups of this warp (butterfly over bits 3-4 only).
    contrib += __shfl_xor_sync(0xffffffffu, contrib, 8);
    contrib += __shfl_xor_sync(0xffffffffu, contrib, 16);

    if ((t & 31) == 0) wsum[t >> 5] = contrib;
    __syncthreads();

    // Final 32-value reduce in warp 0; broadcast scalar to all B=32 outputs.
    if (t < 32) {
        const float b3 = bf3[0];       // only loaded by the threads that use it
        float s = wsum[t];
        s += __shfl_xor_sync(0xffffffffu, s, 1);
        s += __shfl_xor_sync(0xffffffffu, s, 2);
        s += __shfl_xor_sync(0xffffffffu, s, 4);
        s += __shfl_xor_sync(0xffffffffu, s, 8);
        s += __shfl_xor_sync(0xffffffffu, s, 16);
        out[t] = s + b3;
    }
}

extern "C" void kernel_launch(void* const* d_in, const int* in_sizes, int n_in,
                              void* d_out, int out_size) {
    (void)out_size;

    // Anchor: Wf1 has 128*32768 = 4194304 elements, unique by far.
    int wf1 = 26;
    for (int k = 0; k < n_in; ++k) {
        if (in_sizes[k] == 128 * 32768) { wf1 = k; break; }
    }

    const float* bf1 = (const float*)d_in[wf1 + 1];
    const float* Wf2 = (const float*)d_in[wf1 + 2];
    const float* bf2 = (const float*)d_in[wf1 + 3];
    const float* Wf3 = (const float*)d_in[wf1 + 4];
    const float* bf3 = (const float*)d_in[wf1 + 5];
    float* out = (float*)d_out;

    TF2N_35347580846484_kernel<<<1, 1024>>>(bf1, Wf2, bf2, Wf3, bf3, out);
}

// round 11
// speedup vs baseline: 1.0096x; 1.0096x over previous
#include <cuda_runtime.h>

// Algebraic reduction of the reference (verified R2-R9, rel_err 1.41e-7):
//   tr = (op - op) * weight == 0 exactly  =>  real_sum == 0  =>
//   out[b] = relu(relu(bf1) @ Wf2^T + bf2) @ Wf3^T + bf3   (same scalar, all b)
// Live inputs: bf1, Wf2(128x128), bf2, Wf3, bf3 — located by anchoring on
// Wf1's unique element count (128*32768) in in_sizes.
//
// R10 resubmit (R11) after infra failure — terminal kernel: R8/R9 winning
// structure — 1024 thr, 8 thr/row, 8x independent LDG.128/thread (one
// concurrent load window), predicate-free row fold, single barrier. Tail
// trim: after the final butterfly all 32 lanes hold the scalar, so lanes
// 0-7 emit the 32 outputs as 8x STG.128.
// Session: 15.1 -> 8.4 -> 7.0 -> 6.66 us; R8/R9 neutral pair confirms the
// single-block T_ovh floor (~5000 cyc + ~2000 cyc work at NAT clock).

#define PF 128

__global__ __launch_bounds__(1024, 1)
void TF2N_35347580846484_kernel(const float* __restrict__ bf1,
                                const float* __restrict__ Wf2,
                                const float* __restrict__ bf2,
                                const float* __restrict__ Wf3,
                                const float* __restrict__ bf3,
                                float* __restrict__ out) {
    __shared__ float wsum[32];         // per-warp partial sums

    const int t = threadIdx.x;
    const int r = t >> 3;              // output row 0..127
    const int c = t & 7;               // 16-col chunk within the row

    // Issue ALL global loads up front; every one is independent.
    const float4* __restrict__ wp =
        reinterpret_cast<const float4*>(Wf2 + r * PF + c * 16);
    const float4* __restrict__ zp =
        reinterpret_cast<const float4*>(bf1 + c * 16);
    const float4 w0 = wp[0];
    const float4 w1 = wp[1];
    const float4 w2 = wp[2];
    const float4 w3 = wp[3];
    float4 a0 = zp[0];
    float4 a1 = zp[1];
    float4 a2 = zp[2];
    float4 a3 = zp[3];
    const float b2  = bf2[r];
    const float w3r = Wf3[r];

    // relu(bf1) in registers
    a0.x = fmaxf(a0.x, 0.0f); a0.y = fmaxf(a0.y, 0.0f);
    a0.z = fmaxf(a0.z, 0.0f); a0.w = fmaxf(a0.w, 0.0f);
    a1.x = fmaxf(a1.x, 0.0f); a1.y = fmaxf(a1.y, 0.0f);
    a1.z = fmaxf(a1.z, 0.0f); a1.w = fmaxf(a1.w, 0.0f);
    a2.x = fmaxf(a2.x, 0.0f); a2.y = fmaxf(a2.y, 0.0f);
    a2.z = fmaxf(a2.z, 0.0f); a2.w = fmaxf(a2.w, 0.0f);
    a3.x = fmaxf(a3.x, 0.0f); a3.y = fmaxf(a3.y, 0.0f);
    a3.z = fmaxf(a3.z, 0.0f); a3.w = fmaxf(a3.w, 0.0f);

    // 16-element partial dot: Wf2[r, c*16 .. c*16+15] . relu(bf1)[c*16..]
    float acc;
    acc = w0.x * a0.x;
    acc = fmaf(w0.y, a0.y, acc);
    acc = fmaf(w0.z, a0.z, acc);
    acc = fmaf(w0.w, a0.w, acc);
    acc = fmaf(w1.x, a1.x, acc);
    acc = fmaf(w1.y, a1.y, acc);
    acc = fmaf(w1.z, a1.z, acc);
    acc = fmaf(w1.w, a1.w, acc);
    acc = fmaf(w2.x, a2.x, acc);
    acc = fmaf(w2.y, a2.y, acc);
    acc = fmaf(w2.z, a2.z, acc);
    acc = fmaf(w2.w, a2.w, acc);
    acc = fmaf(w3.x, a3.x, acc);
    acc = fmaf(w3.y, a3.y, acc);
    acc = fmaf(w3.z, a3.z, acc);
    acc = fmaf(w3.w, a3.w, acc);

    // Reduce the 8 chunk-partials of this row; all 8 lanes end with the sum.
    acc += __shfl_xor_sync(0xffffffffu, acc, 1);
    acc += __shfl_xor_sync(0xffffffffu, acc, 2);
    acc += __shfl_xor_sync(0xffffffffu, acc, 4);

    // Every lane of the row group folds bias + relu + Wf3 weight (identical
    // value on all 8 lanes). The cross-group butterfly below sums one
    // representative per row group at each lane position -> exact 4-row sum.
    float contrib = fmaxf(acc + b2, 0.0f) * w3r;

    // Sum the 4 row-groups of this warp (butterfly over bits 3-4 only).
    contrib += __shfl_xor_sync(0xffffffffu, contrib, 8);
    contrib += __shfl_xor_sync(0xffffffffu, contrib, 16);

    if ((t & 31) == 0) wsum[t >> 5] = contrib;
    __syncthreads();

    // Final 32-value reduce in warp 0; broadcast scalar to all B=32 outputs.
    if (t < 32) {
        const float b3 = bf3[0];       // only loaded by the threads that use it
        float s = wsum[t];
        s += __shfl_xor_sync(0xffffffffu, s, 1);
        s += __shfl_xor_sync(0xffffffffu, s, 2);
        s += __shfl_xor_sync(0xffffffffu, s, 4);
        s += __shfl_xor_sync(0xffffffffu, s, 8);
        s += __shfl_xor_sync(0xffffffffu, s, 16);
        s += b3;
        // All 32 lanes hold s; lanes 0-7 store the 32 outputs as 8x STG.128.
        if (t < 8) {
            float4 v = make_float4(s, s, s, s);
            reinterpret_cast<float4*>(out)[t] = v;
        }
    }
}

extern "C" void kernel_launch(void* const* d_in, const int* in_sizes, int n_in,
                              void* d_out, int out_size) {
    (void)out_size;

    // Anchor: Wf1 has 128*32768 = 4194304 elements, unique by far.
    int wf1 = 26;
    for (int k = 0; k < n_in; ++k) {
        if (in_sizes[k] == 128 * 32768) { wf1 = k; break; }
    }

    const float* bf1 = (const float*)d_in[wf1 + 1];
    const float* Wf2 = (const float*)d_in[wf1 + 2];
    const float* bf2 = (const float*)d_in[wf1 + 3];
    const float* Wf3 = (const float*)d_in[wf1 + 4];
    const float* bf3 = (const float*)d_in[wf1 + 5];
    float* out = (float*)d_out;

    TF2N_35347580846484_kernel<<<1, 1024>>>(bf1, Wf2, bf2, Wf3, bf3, out);
}

// round 12
// speedup vs baseline: 1.0244x; 1.0146x over previous
#include <cuda_runtime.h>

// ============================================================================
// TERMINAL KERNEL (session best: 6.66us, rel_err 1.41e-7)
//
// Algebraic reduction of the reference (verified R2-R11):
//   The fusion loop computes tr = (op - op) * weight == 0 exactly for finite
//   op, so real_sum == 0 and the entire LSTM/MLP/phase/outer-product graph is
//   dead. Output = relu(relu(bf1) @ Wf2^T + bf2) @ Wf3^T + bf3, one scalar
//   broadcast to all B=32 rows. Live inputs: bf1, Wf2(128x128), bf2, Wf3,
//   bf3 — anchored on Wf1's unique element count (128*32768) in in_sizes.
//
// Shape (proven optimal over R3-R11): one block, 1024 threads, 8 threads per
// output row, 8x independent LDG.128 per thread so ALL 64KB of Wf2 + bf1 fly
// in a single memory-latency window; no barrier before the FMA chain;
// predicate-free shfl-butterfly reduce (row fold replicated across the 8-lane
// group, cross-group butterfly over bits 3-4 only); one __syncthreads; final
// 32-partial reduce in warp 0; outputs emitted as 8x STG.128.
//
// Falsified alternatives: 128-thr serial row walk (14us), 512-thr fat warps
// (7.1us), smem z1 staging (+0.5us). Remaining time is the single-block
// launch/drain floor (~5000 cyc) — not addressable by kernel content.
// ============================================================================

#define PF 128

__global__ __launch_bounds__(1024, 1)
void TF2N_35347580846484_kernel(const float* __restrict__ bf1,
                                const float* __restrict__ Wf2,
                                const float* __restrict__ bf2,
                                const float* __restrict__ Wf3,
                                const float* __restrict__ bf3,
                                float* __restrict__ out) {
    __shared__ float wsum[32];         // per-warp partial sums

    const int t = threadIdx.x;
    const int r = t >> 3;              // output row 0..127
    const int c = t & 7;               // 16-col chunk within the row

    // Issue ALL global loads up front; every one is independent.
    const float4* __restrict__ wp =
        reinterpret_cast<const float4*>(Wf2 + r * PF + c * 16);
    const float4* __restrict__ zp =
        reinterpret_cast<const float4*>(bf1 + c * 16);
    const float4 w0 = wp[0];
    const float4 w1 = wp[1];
    const float4 w2 = wp[2];
    const float4 w3 = wp[3];
    float4 a0 = zp[0];
    float4 a1 = zp[1];
    float4 a2 = zp[2];
    float4 a3 = zp[3];
    const float b2  = bf2[r];
    const float w3r = Wf3[r];

    // relu(bf1) in registers
    a0.x = fmaxf(a0.x, 0.0f); a0.y = fmaxf(a0.y, 0.0f);
    a0.z = fmaxf(a0.z, 0.0f); a0.w = fmaxf(a0.w, 0.0f);
    a1.x = fmaxf(a1.x, 0.0f); a1.y = fmaxf(a1.y, 0.0f);
    a1.z = fmaxf(a1.z, 0.0f); a1.w = fmaxf(a1.w, 0.0f);
    a2.x = fmaxf(a2.x, 0.0f); a2.y = fmaxf(a2.y, 0.0f);
    a2.z = fmaxf(a2.z, 0.0f); a2.w = fmaxf(a2.w, 0.0f);
    a3.x = fmaxf(a3.x, 0.0f); a3.y = fmaxf(a3.y, 0.0f);
    a3.z = fmaxf(a3.z, 0.0f); a3.w = fmaxf(a3.w, 0.0f);

    // 16-element partial dot: Wf2[r, c*16 .. c*16+15] . relu(bf1)[c*16..]
    float acc;
    acc = w0.x * a0.x;
    acc = fmaf(w0.y, a0.y, acc);
    acc = fmaf(w0.z, a0.z, acc);
    acc = fmaf(w0.w, a0.w, acc);
    acc = fmaf(w1.x, a1.x, acc);
    acc = fmaf(w1.y, a1.y, acc);
    acc = fmaf(w1.z, a1.z, acc);
    acc = fmaf(w1.w, a1.w, acc);
    acc = fmaf(w2.x, a2.x, acc);
    acc = fmaf(w2.y, a2.y, acc);
    acc = fmaf(w2.z, a2.z, acc);
    acc = fmaf(w2.w, a2.w, acc);
    acc = fmaf(w3.x, a3.x, acc);
    acc = fmaf(w3.y, a3.y, acc);
    acc = fmaf(w3.z, a3.z, acc);
    acc = fmaf(w3.w, a3.w, acc);

    // Reduce the 8 chunk-partials of this row; all 8 lanes end with the sum.
    acc += __shfl_xor_sync(0xffffffffu, acc, 1);
    acc += __shfl_xor_sync(0xffffffffu, acc, 2);
    acc += __shfl_xor_sync(0xffffffffu, acc, 4);

    // Every lane of the row group folds bias + relu + Wf3 weight (identical
    // value on all 8 lanes). The cross-group butterfly below sums one
    // representative per row group at each lane position -> exact 4-row sum.
    float contrib = fmaxf(acc + b2, 0.0f) * w3r;

    // Sum the 4 row-groups of this warp (butterfly over bits 3-4 only).
    contrib += __shfl_xor_sync(0xffffffffu, contrib, 8);
    contrib += __shfl_xor_sync(0xffffffffu, contrib, 16);

    if ((t & 31) == 0) wsum[t >> 5] = contrib;
    __syncthreads();

    // Final 32-value reduce in warp 0; broadcast scalar to all B=32 outputs.
    if (t < 32) {
        const float b3 = bf3[0];       // only loaded by the threads that use it
        float s = wsum[t];
        s += __shfl_xor_sync(0xffffffffu, s, 1);
        s += __shfl_xor_sync(0xffffffffu, s, 2);
        s += __shfl_xor_sync(0xffffffffu, s, 4);
        s += __shfl_xor_sync(0xffffffffu, s, 8);
        s += __shfl_xor_sync(0xffffffffu, s, 16);
        s += b3;
        // All 32 lanes hold s; lanes 0-7 store the 32 outputs as 8x STG.128.
        if (t < 8) {
            float4 v = make_float4(s, s, s, s);
            reinterpret_cast<float4*>(out)[t] = v;
        }
    }
}

extern "C" void kernel_launch(void* const* d_in, const int* in_sizes, int n_in,
                              void* d_out, int out_size) {
    (void)out_size;

    // Anchor: Wf1 has 128*32768 = 4194304 elements, unique by far.
    int wf1 = 26;
    for (int k = 0; k < n_in; ++k) {
        if (in_sizes[k] == 128 * 32768) { wf1 = k; break; }
    }

    const float* bf1 = (const float*)d_in[wf1 + 1];
    const float* Wf2 = (const float*)d_in[wf1 + 2];
    const float* bf2 = (const float*)d_in[wf1 + 3];
    const float* Wf3 = (const float*)d_in[wf1 + 4];
    const float* bf3 = (const float*)d_in[wf1 + 5];
    float* out = (float*)d_out;

    TF2N_35347580846484_kernel<<<1, 1024>>>(bf1, Wf2, bf2, Wf3, bf3, out);
}